// round 17
// baseline (speedup 1.0000x reference)
#include <cuda_runtime.h>
#include <cuda_fp16.h>
#include <cstdint>
#include <cstddef>

// ---------------- problem constants ----------------
static constexpr int Bm = 1024;     // batch rows
static constexpr int Dk = 512;      // feature dim (K)
static constexpr int Cn = 100000;   // classes (N)
static constexpr float S_s = 30.0f;
static constexpr float M_m = 0.4f;

// GEMM config
#define BMT 128
#define BNT 128
#define BKT 32
static constexpr int NCHUNK = Dk / BKT;   // 16
static constexpr int STAGES = 4;
static constexpr int A_STAGE = BMT * BKT * 2;      // 8192 B (fp16)
static constexpr int W_STAGE = BKT * BNT * 4;      // 16384 B (fp32 staging)
static constexpr int B_BYTES = BKT * BNT * 2;      // 8192 B (fp16, single buffer)
static constexpr int OFF_W = STAGES * A_STAGE;                 // 32768
static constexpr int OFF_BH = OFF_W + STAGES * W_STAGE;        // 98304
static constexpr int SMEM_BYTES = OFF_BH + B_BYTES;            // 106496 (104KB)

// ---------------- device scratch (no runtime allocation allowed) ----------------
__device__ __half g_Xh[Bm * Dk];                      // normalized x, fp16
__device__ float g_rowsum[Bm];                        // sum_c exp(S*cos)
__device__ float g_lsum;                              // loss partial-sum accumulator
__device__ int   g_ldone;                             // loss block ticket counter
__device__ float g_cos_scratch[(size_t)Bm * (size_t)Cn]; // fallback cossim store

// ---------------- helpers ----------------
__device__ __forceinline__ uint32_t f2h2(float a, float b) {
    __half2 h = __floats2half2_rn(a, b);
    return *reinterpret_cast<uint32_t*>(&h);
}

__device__ __forceinline__ void mma16(float* d, const uint32_t* a, const uint32_t* b) {
    asm volatile(
        "mma.sync.aligned.m16n8k16.row.col.f32.f16.f16.f32 "
        "{%0,%1,%2,%3}, {%4,%5,%6,%7}, {%8,%9}, {%0,%1,%2,%3};\n"
        : "+f"(d[0]), "+f"(d[1]), "+f"(d[2]), "+f"(d[3])
        : "r"(a[0]), "r"(a[1]), "r"(a[2]), "r"(a[3]), "r"(b[0]), "r"(b[1]));
}
__device__ __forceinline__ void ldsm4(uint32_t* r, uint32_t addr) {
    asm volatile("ldmatrix.sync.aligned.m8n8.x4.shared.b16 {%0,%1,%2,%3}, [%4];"
                 : "=r"(r[0]), "=r"(r[1]), "=r"(r[2]), "=r"(r[3]) : "r"(addr));
}
__device__ __forceinline__ void ldsm4t(uint32_t* r, uint32_t addr) {
    asm volatile("ldmatrix.sync.aligned.m8n8.x4.trans.shared.b16 {%0,%1,%2,%3}, [%4];"
                 : "=r"(r[0]), "=r"(r[1]), "=r"(r[2]), "=r"(r[3]) : "r"(addr));
}
__device__ __forceinline__ void cp16(uint32_t smem_dst, const void* gsrc) {
    asm volatile("cp.async.cg.shared.global [%0], [%1], 16;"
                 :: "r"(smem_dst), "l"(gsrc) : "memory");
}
__device__ __forceinline__ void cp_commit() {
    asm volatile("cp.async.commit_group;" ::: "memory");
}
template <int N>
__device__ __forceinline__ void cp_wait() {
    asm volatile("cp.async.wait_group %0;" :: "n"(N) : "memory");
}

// swizzled byte offsets inside the smem tiles (16B cell granularity)
// A tile: 128 rows x 32 halfs (64B/row = 4 cells): cell ^= (row>>1)&3
__device__ __forceinline__ int a_byte(int r, int c) {
    return r * 64 + ((c ^ ((r >> 1) & 3)) << 4);
}
// B tile (fp16): 32 k-rows x 128 halfs (256B/row = 16 cells): cell ^= k&7
__device__ __forceinline__ int b_byte(int k, int c) {
    return k * 256 + ((c ^ (k & 7)) << 4);
}
// W fp32 staging: 32 k-rows x 128 floats (512B/row = 32 cells).
// Thread (k, g) owns cells g and g+16: per 8-lane LDS phase all cells distinct mod 8.
__device__ __forceinline__ int w_byte(int k, int g, int half) {
    return k * 512 + ((g + (half << 4)) << 4);
}

// ---------------- kernel 1: L2-normalize rows of x -> fp16; zero accumulators ------
__global__ void normalize_x_kernel(const float* __restrict__ x) {
    const int b = blockIdx.x;           // 1024 blocks
    const int t = threadIdx.x;          // 128 threads
    float4 v = reinterpret_cast<const float4*>(x + (size_t)b * Dk)[t];
    float ss = v.x * v.x + v.y * v.y + v.z * v.z + v.w * v.w;
    #pragma unroll
    for (int o = 16; o > 0; o >>= 1) ss += __shfl_xor_sync(0xffffffffu, ss, o);
    __shared__ float ws[4];
    if ((t & 31) == 0) ws[t >> 5] = ss;
    __syncthreads();
    const float tot = ws[0] + ws[1] + ws[2] + ws[3];
    const float inv = 1.0f / fmaxf(sqrtf(tot), 1e-12f);
    uint2 st;
    st.x = f2h2(v.x * inv, v.y * inv);
    st.y = f2h2(v.z * inv, v.w * inv);
    reinterpret_cast<uint2*>(g_Xh + (size_t)b * Dk)[t] = st;
    if (t == 0) g_rowsum[b] = 0.0f;
    if (b == 0 && t == 0) { g_lsum = 0.0f; g_ldone = 0; }
}

// ---------------- kernel 2: fp16 GEMM consuming fp32 W via cp.async staging --------
// Per chunk: cp.async stages fp32 W in smem; a short convert pass builds the fp16
// B tile + per-column sum-of-squares (winv built in-CTA). No separate wprep pass.
__global__ void __launch_bounds__(256, 2)
gemm_cos_kernel(const float* __restrict__ Wp, float* __restrict__ outp) {
    extern __shared__ __align__(128) uint8_t smem[];
    uint8_t* As = smem;                    // 4 x 8KB fp16 (cp.async)
    uint8_t* Ws = smem + OFF_W;            // 4 x 16KB fp32 staging (cp.async)
    uint8_t* Bh = smem + OFF_BH;           // 1 x 8KB fp16 B tile

    float* __restrict__ outc = outp ? outp : g_cos_scratch;

    const int tid  = threadIdx.x;
    const int lane = tid & 31;
    const int g    = lane >> 2;
    const int t    = lane & 3;
    const int warp = tid >> 5;
    const int wm   = warp & 1;    // 2 warps in M (64 rows each)
    const int wn   = warp >> 1;   // 4 warps in N (32 cols each)
    const int bN   = blockIdx.y * BNT;
    const int bM   = blockIdx.x * BMT;

    const uint32_t sA0 = (uint32_t)__cvta_generic_to_shared(As);
    const uint32_t sW0 = (uint32_t)__cvta_generic_to_shared(Ws);
    const uint32_t sBh = (uint32_t)__cvta_generic_to_shared(Bh);

    // ---- A load coordinates (cp.async fp16, same as R14) ----
    const int arow = tid >> 1;
    const int ac0  = (tid & 1) * 2;
    const __half* Abase = g_Xh + (size_t)(bM + arow) * Dk + ac0 * 8;

    // ---- W load/convert coordinates: thread owns 2 k-rows x 8 n ----
    const int kpair = tid >> 4;         // 0..15 -> k rows {2kp, 2kp+1}
    const int ngrp  = tid & 15;         // n block: n0..n0+7
    const int n0    = bN + ngrp * 8;
    const bool nvalid = (n0 + 8 <= Cn); // Cn % 8 == 0 -> all-or-nothing per thread

    auto issue_stage = [&](int s) {     // group s = {A(s), W(s)}
        const int buf = s & (STAGES - 1);
        const int kc  = s * BKT;
        const uint32_t dA = sA0 + buf * A_STAGE;
        cp16(dA + a_byte(arow, ac0),     Abase + kc);
        cp16(dA + a_byte(arow, ac0 + 1), Abase + kc + 8);
        if (nvalid) {
            const uint32_t dW = sW0 + buf * W_STAGE;
            #pragma unroll
            for (int kr = 0; kr < 2; ++kr) {
                const int k = 2 * kpair + kr;
                const float* src = Wp + (size_t)(kc + k) * Cn + n0;
                cp16(dW + w_byte(k, ngrp, 0), src);
                cp16(dW + w_byte(k, ngrp, 1), src + 4);
            }
        }
    };

    float sumsq[8];
    #pragma unroll
    for (int j = 0; j < 8; ++j) sumsq[j] = 0.0f;

    auto convert = [&](int s) {          // W fp32 stage (s) -> fp16 B tile + sumsq
        const uint8_t* Wb = Ws + (s & (STAGES - 1)) * W_STAGE;
        #pragma unroll
        for (int kr = 0; kr < 2; ++kr) {
            const int k = 2 * kpair + kr;
            uint4 h;
            if (nvalid) {
                const float4 a = *reinterpret_cast<const float4*>(Wb + w_byte(k, ngrp, 0));
                const float4 b = *reinterpret_cast<const float4*>(Wb + w_byte(k, ngrp, 1));
                sumsq[0] = fmaf(a.x, a.x, sumsq[0]);
                sumsq[1] = fmaf(a.y, a.y, sumsq[1]);
                sumsq[2] = fmaf(a.z, a.z, sumsq[2]);
                sumsq[3] = fmaf(a.w, a.w, sumsq[3]);
                sumsq[4] = fmaf(b.x, b.x, sumsq[4]);
                sumsq[5] = fmaf(b.y, b.y, sumsq[5]);
                sumsq[6] = fmaf(b.z, b.z, sumsq[6]);
                sumsq[7] = fmaf(b.w, b.w, sumsq[7]);
                h.x = f2h2(a.x, a.y); h.y = f2h2(a.z, a.w);
                h.z = f2h2(b.x, b.y); h.w = f2h2(b.z, b.w);
            } else {
                h = make_uint4(0, 0, 0, 0);
            }
            *reinterpret_cast<uint4*>(Bh + b_byte(k, ngrp)) = h;
        }
    };

    float acc[4][4][4];
    #pragma unroll
    for (int i = 0; i < 4; ++i)
        #pragma unroll
        for (int j = 0; j < 4; ++j)
            #pragma unroll
            for (int k = 0; k < 4; ++k) acc[i][j][k] = 0.0f;

    // per-lane ldmatrix address components
    const int rl = lane & 15;     // row within 16-row tile
    const int cp = lane >> 4;     // cell selector (second half of lanes)

    auto compute_chunk = [&](int buf) {
        const uint32_t sAb = sA0 + buf * A_STAGE;
        #pragma unroll
        for (int ks = 0; ks < 2; ++ks) {
            uint32_t af[4][4];
            uint32_t bf[4][2];
            #pragma unroll
            for (int mt = 0; mt < 4; ++mt)
                ldsm4(af[mt], sAb + a_byte(wm * 64 + mt * 16 + rl, ks * 2 + cp));
            #pragma unroll
            for (int j = 0; j < 2; ++j)
                ldsm4t(&bf[2 * j][0], sBh + b_byte(ks * 16 + rl, wn * 4 + 2 * j + cp));
            #pragma unroll
            for (int mt = 0; mt < 4; ++mt)
                #pragma unroll
                for (int nt = 0; nt < 4; ++nt)
                    mma16(acc[mt][nt], af[mt], bf[nt]);
        }
    };

    // ---- prologue: stage chunks 0..2 ----
    issue_stage(0); cp_commit();
    issue_stage(1); cp_commit();
    issue_stage(2); cp_commit();

    // ---- mainloop ----
    #pragma unroll 4
    for (int it = 0; it < NCHUNK; ++it) {
        cp_wait<2>();
        __syncthreads();                  // stage(it) ready; prior compute done
        if (it + 3 < NCHUNK) issue_stage(it + 3);
        cp_commit();                      // empty groups at tail keep wait math valid
        convert(it);                      // fp32 stage -> fp16 B tile (+sumsq)
        __syncthreads();                  // B tile visible
        compute_chunk(it & (STAGES - 1));
    }

    // ---- build winv in smem from per-thread sumsq ----
    cp_wait<0>();
    __syncthreads();                      // mainloop smem reads done; reuse A region
    float* colss  = reinterpret_cast<float*>(smem);          // [128][17] padded
    float* winv_s = reinterpret_cast<float*>(smem + 8704);   // 128 floats
    #pragma unroll
    for (int j = 0; j < 8; ++j)
        colss[(ngrp * 8 + j) * 17 + kpair] = sumsq[j];
    __syncthreads();
    if (tid < BNT) {
        float s = 0.0f;
        #pragma unroll
        for (int r = 0; r < 16; ++r) s += colss[tid * 17 + r];
        winv_s[tid] = 1.0f / fmaxf(sqrtf(s), 1e-12f);
    }
    __syncthreads();

    // -------- fused epilogue: scale by 1/||w_c||, clip, store, accumulate exp-sums ----
    float rsum[4][2];
    #pragma unroll
    for (int mt = 0; mt < 4; ++mt) { rsum[mt][0] = 0.0f; rsum[mt][1] = 0.0f; }

    #pragma unroll
    for (int mt = 0; mt < 4; ++mt) {
        const int gr0 = bM + wm * 64 + mt * 16 + g;
        #pragma unroll
        for (int nt = 0; nt < 4; ++nt) {
            const int nl = wn * 32 + nt * 8 + t * 2;
            const int gc = bN + nl;
            if (gc < Cn) {
                const float iw0 = winv_s[nl];
                const float iw1 = winv_s[nl + 1];
                float c0 = fminf(fmaxf(acc[mt][nt][0] * iw0, -1.0f), 1.0f);
                float c1 = fminf(fmaxf(acc[mt][nt][1] * iw1, -1.0f), 1.0f);
                float c2 = fminf(fmaxf(acc[mt][nt][2] * iw0, -1.0f), 1.0f);
                float c3 = fminf(fmaxf(acc[mt][nt][3] * iw1, -1.0f), 1.0f);
                *reinterpret_cast<float2*>(&outc[(size_t)gr0 * Cn + gc]) = make_float2(c0, c1);
                *reinterpret_cast<float2*>(&outc[(size_t)(gr0 + 8) * Cn + gc]) = make_float2(c2, c3);
                rsum[mt][0] += __expf(S_s * c0) + __expf(S_s * c1);
                rsum[mt][1] += __expf(S_s * c2) + __expf(S_s * c3);
            }
        }
    }
    #pragma unroll
    for (int mt = 0; mt < 4; ++mt) {
        #pragma unroll
        for (int h = 0; h < 2; ++h) {
            float v = rsum[mt][h];
            v += __shfl_xor_sync(0xffffffffu, v, 1);
            v += __shfl_xor_sync(0xffffffffu, v, 2);
            if (t == 0) {
                const int gr = bM + wm * 64 + mt * 16 + g + h * 8;
                atomicAdd(&g_rowsum[gr], v);
            }
        }
    }
}

// ---------------- kernel 3: parallel per-row loss (reads cossim) ----------------
__global__ void loss_kernel(const float* __restrict__ cosp_param,
                            const int* __restrict__ lbl32,
                            float* __restrict__ loss_out) {
    const float* cosp = cosp_param ? cosp_param : g_cos_scratch;
    const int b = blockIdx.x * 128 + threadIdx.x;   // grid 8 x 128 threads

    __shared__ int nz;
    if (threadIdx.x == 0) nz = 0;
    __syncthreads();
    if (lbl32[2 * b + 1] != 0) atomicOr(&nz, 1);
    __syncthreads();

    int label;
    if (nz == 0) label = (int)(reinterpret_cast<const long long*>(lbl32)[b]);
    else         label = lbl32[b];

    const float tgt  = cosp[(size_t)b * Cn + label];
    const float excl = g_rowsum[b] - __expf(S_s * tgt);
    const float num  = S_s * (tgt - M_m);
    const float L    = num - logf(expf(num) + excl);

    float v = L;
    #pragma unroll
    for (int o = 16; o > 0; o >>= 1) v += __shfl_xor_sync(0xffffffffu, v, o);
    __shared__ float red[4];
    if ((threadIdx.x & 31) == 0) red[threadIdx.x >> 5] = v;
    __syncthreads();
    if (threadIdx.x == 0) {
        const float s = red[0] + red[1] + red[2] + red[3];
        atomicAdd(&g_lsum, s);
        __threadfence();
        const int tkt = atomicAdd(&g_ldone, 1);
        if (tkt == (int)gridDim.x - 1) {
            const float total = atomicAdd(&g_lsum, 0.0f);
            loss_out[0] = -(total / (float)Bm);
        }
    }
}

// ---------------- launch ----------------
extern "C" void kernel_launch(void* const* d_in, const int* in_sizes, int n_in,
                              void* d_out, int out_size) {
    const float* x   = (const float*)d_in[0];
    const float* W   = (const float*)d_in[1];
    const int*   lbl = (const int*)d_in[2];
    float* out = (float*)d_out;

    const long long BC = (long long)Bm * (long long)Cn;   // 102,400,000
    const bool cos_in_out = ((long long)out_size >= BC);

    static bool attr_set = false;
    if (!attr_set) {
        cudaFuncSetAttribute(gemm_cos_kernel,
                             cudaFuncAttributeMaxDynamicSharedMemorySize, SMEM_BYTES);
        attr_set = true;
    }

    normalize_x_kernel<<<Bm, 128>>>(x);

    // grid: x = M-blocks (8, fast-moving), y = N-blocks (782) -> W tiles L2-shared
    dim3 gg(Bm / BMT, (Cn + BNT - 1) / BNT);   // (8, 782)
    gemm_cos_kernel<<<gg, 256, SMEM_BYTES>>>(W, cos_in_out ? out : nullptr);

    if (cos_in_out && (long long)out_size >= BC + 1) {
        loss_kernel<<<8, 128>>>(out, lbl, out + BC);
    } else if (!cos_in_out && out_size >= 1) {
        loss_kernel<<<8, 128>>>(nullptr, lbl, out);
    }
}